// round 10
// baseline (speedup 1.0000x reference)
#include <cuda_runtime.h>
#include <cstdint>
#include <cstring>
#include <vector>
#include <algorithm>

// ---------------------------------------------------------------------------
// CLOPLayer: out[b,c,i] = x[b,c,idx[i]], idx fixed (JAX threefry seed 42 +
// sequential neighbor-swap scan), recomputed bit-exact on the HOST each call.
//
// R10: single fused kernel (R9 structure) with BAND=112 (2 bands/plane):
//  - halo read ratio 124/112 = 1.11 (was 68/56 = 1.21)  -> ~8MB less DRAM
//  - 768 blocks instead of 1536 -> half the per-block overhead, 2.59 waves
//  - smem 111KB -> 2 blocks/SM, 32 warps
// First 16 scheduled blocks also copy the host-resident uint16 idx table into
// g_idxl via ATS (GB300 C2C) under the x-window DMA; waiters spin on flags.
// Replay-deterministic: copy re-executes identically; content bit-identical.
// ---------------------------------------------------------------------------

#define GH 224
#define GW 224
#define HW (GH * GW)          // 50176
#define NPLANES 384           // 128 * 3
#define BAND 112
#define NBANDS (GH / BAND)    // 2
#define BANDW (BAND * GW)     // 25088
#define BANDW4 (BANDW / 4)    // 6272
#define NT 512
#define GITER ((BANDW4 + NT - 1) / NT)   // 13 (last partial)
#define HW16 (HW / 8)         // 6272 uint4 units of the uint16 idx table
#define NCOPY 16
#define CHUNK16 (HW16 / NCOPY)  // 392 uint4 per chunk

__device__ unsigned short g_idxl[HW];   // window-relative indices
__device__ unsigned int g_flag[NCOPY];  // zero-init; set once content is live

static __device__ __forceinline__ uint32_t smem_u32(const void* p) {
    uint32_t a;
    asm("{ .reg .u64 t; cvta.to.shared.u64 t, %1; cvt.u32.u64 %0, t; }"
        : "=r"(a) : "l"(p));
    return a;
}
static __device__ __forceinline__ void mbar_init(uint32_t mb, uint32_t cnt) {
    asm volatile("mbarrier.init.shared.b64 [%0], %1;" :: "r"(mb), "r"(cnt)
                 : "memory");
}
static __device__ __forceinline__ void mbar_expect_tx(uint32_t mb, uint32_t tx) {
    asm volatile("mbarrier.arrive.expect_tx.shared.b64 _, [%0], %1;"
                 :: "r"(mb), "r"(tx) : "memory");
}
static __device__ __forceinline__ void bulk_g2s(uint32_t dst, const void* src,
                                                uint32_t bytes, uint32_t mb) {
    asm volatile(
        "cp.async.bulk.shared::cluster.global.mbarrier::complete_tx::bytes "
        "[%0], [%1], %2, [%3];"
        :: "r"(dst), "l"(src), "r"(bytes), "r"(mb) : "memory");
}
static __device__ __forceinline__ void mbar_wait(uint32_t mb, uint32_t phase) {
    asm volatile(
        "{\n\t"
        ".reg .pred P;\n\t"
        "WAIT_%=: \n\t"
        "mbarrier.try_wait.parity.acquire.cta.shared::cta.b64 P, [%0], %1, 0x989680;\n\t"
        "@P bra.uni DONE_%=;\n\t"
        "bra.uni WAIT_%=;\n\t"
        "DONE_%=: \n\t"
        "}"
        :: "r"(mb), "r"(phase) : "memory");
}
static __device__ __forceinline__ unsigned int ld_acquire(unsigned int* p) {
    unsigned int v;
    asm volatile("ld.global.acquire.gpu.u32 %0, [%1];" : "=r"(v) : "l"(p)
                 : "memory");
    return v;
}

// ---- fused banded gather + idx delivery, compile-time window height Lc -----
template <int Lc>
__global__ __launch_bounds__(NT)
void clop_band_t(const float* __restrict__ x, float* __restrict__ out,
                 const uint4* __restrict__ hidx, int do_copy) {
    extern __shared__ float sp[];                 // Lc*GW floats, row-major
    __shared__ __align__(8) unsigned long long mbar_s;

    const int plane = blockIdx.x;
    const int band  = blockIdx.y;
    const float* src = x + (size_t)plane * HW;

    int ws = band * BAND - ((Lc - BAND) >> 1);    // toroidal window start row
    if (ws < 0) ws += GH;

    const uint32_t mb = smem_u32(&mbar_s);
    if (threadIdx.x == 0) mbar_init(mb, 1);
    __syncthreads();

    // (1) x-window DMA first — independent of idx
    if (threadIdx.x == 0) {
        constexpr uint32_t TOTAL = (uint32_t)Lc * GW * sizeof(float);
        mbar_expect_tx(mb, TOTAL);
        const int n1 = (GH - ws < Lc) ? (GH - ws) : Lc;   // rows before wrap
        const uint32_t b1 = (uint32_t)n1 * GW * sizeof(float);
        bulk_g2s(smem_u32(sp), src + (size_t)ws * GW, b1, mb);
        if (n1 < Lc) {
            bulk_g2s(smem_u32(sp) + b1, src, TOTAL - b1, mb);
        }
    }

    // (2) copier role: first NCOPY scheduled blocks ship one idx chunk each
    if (do_copy) {
        const int bid = blockIdx.y * gridDim.x + blockIdx.x;
        if (bid < NCOPY) {
            const int base16 = bid * CHUNK16;
            if (threadIdx.x < CHUNK16) {
                reinterpret_cast<uint4*>(g_idxl)[base16 + threadIdx.x] =
                    __ldg(&hidx[base16 + threadIdx.x]);
            }
            __syncthreads();
            if (threadIdx.x == 0) {
                __threadfence();
                atomicExch(&g_flag[bid], 1u);
            }
        }
        if (threadIdx.x < NCOPY) {
            while (ld_acquire(&g_flag[threadIdx.x]) == 0u) __nanosleep(64);
        }
        __syncthreads();
    }

    // (3) prefetch idx for this band into registers, then DMA wait
    const size_t base = (size_t)band * BANDW;
    const ushort4* id4 = reinterpret_cast<const ushort4*>(g_idxl + base);
    ushort4 idbuf[GITER];
#pragma unroll
    for (int u = 0; u < GITER; u++) {
        const int k = threadIdx.x + u * NT;
        if (k < BANDW4) idbuf[u] = __ldg(&id4[k]);
    }

    mbar_wait(mb, 0);

    // (4) gather + coalesced float4 stores
    float4* dst = reinterpret_cast<float4*>(out + (size_t)plane * HW + base);
#pragma unroll
    for (int u = 0; u < GITER; u++) {
        const int k = threadIdx.x + u * NT;
        if (k < BANDW4) {
            const ushort4 id = idbuf[u];
            float4 v;
            v.x = sp[id.x];
            v.y = sp[id.y];
            v.z = sp[id.z];
            v.w = sp[id.w];
            __stcs(&dst[k], v);
        }
    }
}

// ---------------------------------------------------------------------------
// Host-side exact replication of the JAX RNG pipeline (partitionable threefry)
// ---------------------------------------------------------------------------

static inline uint32_t rotl32(uint32_t x, int d) {
    return (x << d) | (x >> (32 - d));
}

struct TFKey { uint32_t hi, lo; };

static void threefry2x32(uint32_t k0, uint32_t k1, uint32_t x0, uint32_t x1,
                         uint32_t* o0, uint32_t* o1) {
    const uint32_t ks0 = k0, ks1 = k1, ks2 = k0 ^ k1 ^ 0x1BD11BDAu;
    static const int ra[4] = {13, 15, 26, 6};
    static const int rb[4] = {17, 29, 16, 24};
    x0 += ks0; x1 += ks1;
    for (int i = 0; i < 4; i++) { x0 += x1; x1 = rotl32(x1, ra[i]); x1 ^= x0; }
    x0 += ks1; x1 += ks2 + 1u;
    for (int i = 0; i < 4; i++) { x0 += x1; x1 = rotl32(x1, rb[i]); x1 ^= x0; }
    x0 += ks2; x1 += ks0 + 2u;
    for (int i = 0; i < 4; i++) { x0 += x1; x1 = rotl32(x1, ra[i]); x1 ^= x0; }
    x0 += ks0; x1 += ks1 + 3u;
    for (int i = 0; i < 4; i++) { x0 += x1; x1 = rotl32(x1, rb[i]); x1 ^= x0; }
    x0 += ks1; x1 += ks2 + 4u;
    for (int i = 0; i < 4; i++) { x0 += x1; x1 = rotl32(x1, ra[i]); x1 ^= x0; }
    x0 += ks2; x1 += ks0 + 5u;
    *o0 = x0; *o1 = x1;
}

static inline TFKey tf_child(TFKey k, uint32_t j) {
    TFKey r; threefry2x32(k.hi, k.lo, 0u, j, &r.hi, &r.lo); return r;
}
static inline uint32_t tf_bits32(TFKey k, uint32_t i) {
    uint32_t a, b; threefry2x32(k.hi, k.lo, 0u, i, &a, &b); return a ^ b;
}

static void compute_host_idx(int* h_idx) {
    const int n = HW;
    TFKey key42 = {0u, 42u};
    TFKey k1 = tf_child(key42, 0u);
    TFKey k2 = tf_child(key42, 1u);

    std::vector<int> order(n);
    for (int i = 0; i < n; i++) order[i] = i;
    {
        TFKey cur = k1;
        std::vector<uint64_t> kv(n);
        std::vector<int> nx(n);
        for (int round = 0; round < 2; round++) {
            TFKey nkey = tf_child(cur, 0u);
            TFKey sub  = tf_child(cur, 1u);
            for (int i = 0; i < n; i++)
                kv[(size_t)i] = ((uint64_t)tf_bits32(sub, (uint32_t)i) << 32) |
                                (uint32_t)i;
            std::sort(kv.begin(), kv.end());
            for (int j = 0; j < n; j++)
                nx[(size_t)j] = order[(size_t)(uint32_t)kv[(size_t)j]];
            order.swap(nx);
            cur = nkey;
        }
    }

    float p0 = (float)(1.0 - 0.3), pq = (float)(0.3 / 4.0);
    float c[5];
    c[0] = p0;
    for (int j = 1; j < 5; j++) c[j] = c[j - 1] + pq;

    std::vector<uint8_t> rs(n);
    for (int i = 0; i < n; i++) {
        uint32_t bits = tf_bits32(k2, (uint32_t)i);
        uint32_t fb = (bits >> 9) | 0x3F800000u;
        float f; std::memcpy(&f, &fb, 4);
        f -= 1.0f;
        float r = c[4] * (1.0f - f);
        int ind = 0;
        while (ind < 5 && c[ind] < r) ind++;
        rs[(size_t)i] = (uint8_t)ind;
    }

    for (int i = 0; i < n; i++) h_idx[i] = i;
    for (int t = 0; t < n; t++) {
        const int a = order[(size_t)t];
        const int r = rs[(size_t)t];
        const int i = a / GW, j = a % GW;
        const int ii = (r == 1) ? (i + 1) % GH : (r == 2) ? (i + GH - 1) % GH : i;
        const int jj = (r == 3) ? (j + 1) % GW : (r == 4) ? (j + GW - 1) % GW : j;
        const int b = (r == 0) ? a : (ii * GW + jj);
        const int va = h_idx[a], vb = h_idx[b];
        h_idx[a] = vb; h_idx[b] = va;
    }
}

// ---------------------------------------------------------------------------

template <int Lc>
static void launch_band(const float* x, float* out, const uint4* hidx,
                        int do_copy) {
    const int smem = Lc * GW * (int)sizeof(float);
    cudaFuncSetAttribute(clop_band_t<Lc>,
                         cudaFuncAttributeMaxDynamicSharedMemorySize, smem);
    dim3 grid(NPLANES, NBANDS);
    clop_band_t<Lc><<<grid, NT, smem>>>(x, out, hidx, do_copy);
}

extern "C" void kernel_launch(void* const* d_in, const int* in_sizes, int n_in,
                              void* d_out, int out_size) {
    (void)in_sizes; (void)n_in; (void)out_size;

    static int h_idx[HW];
    alignas(16) static unsigned short h_idxl[HW];   // ATS-read by the kernel
    compute_host_idx(h_idx);

    // max toroidal row distance from each output row's band window
    int D = 0;
    for (int i = 0; i < HW; i++) {
        const int r_out = i / GW;
        const int bandstart = (r_out / BAND) * BAND;
        const int r_src = h_idx[i] / GW;
        int dist = 0;
        if (r_src >= bandstart && r_src < bandstart + BAND) {
            dist = 0;
        } else {
            int dlo = (bandstart - r_src + GH) % GH;
            int dhi = (r_src - (bandstart + BAND - 1) + GH) % GH;
            dist = dlo < dhi ? dlo : dhi;
        }
        if (dist > D) D = dist;
    }

    // compile-time window heights: L = BAND + 2*Dp, padded up
    int Lc;
    if (D <= 2)       Lc = 116;
    else if (D <= 6)  Lc = 124;
    else if (D <= 10) Lc = 132;
    else              Lc = 224;   // degenerate: whole plane

    // window-relative row-major indices for the padded window
    const int Dp = (Lc - BAND) / 2;
    for (int i = 0; i < HW; i++) {
        const int r_out = i / GW;
        const int ws0 = (r_out / BAND) * BAND - Dp;
        const int r_src = h_idx[i] / GW;
        const int c_src = h_idx[i] % GW;
        int t = r_src - ws0;
        t %= GH; if (t < 0) t += GH;
        h_idxl[i] = (unsigned short)(t * GW + c_src);
    }

    int ats = 0;
    cudaDeviceGetAttribute(&ats, cudaDevAttrPageableMemoryAccess, 0);

    const float* x = (const float*)d_in[0];
    float* out = (float*)d_out;
    const uint4* hidx = reinterpret_cast<const uint4*>(h_idxl);

    if (!ats) {
        cudaMemcpyToSymbolAsync(g_idxl, h_idxl, sizeof(h_idxl), 0,
                                cudaMemcpyHostToDevice, 0);
    }
    const int do_copy = ats ? 1 : 0;

    if (Lc == 116)      launch_band<116>(x, out, hidx, do_copy);
    else if (Lc == 124) launch_band<124>(x, out, hidx, do_copy);
    else if (Lc == 132) launch_band<132>(x, out, hidx, do_copy);
    else                launch_band<224>(x, out, hidx, do_copy);
}

// round 11
// speedup vs baseline: 1.0519x; 1.0519x over previous
#include <cuda_runtime.h>
#include <cstdint>
#include <cstring>
#include <vector>
#include <algorithm>

// ---------------------------------------------------------------------------
// CLOPLayer: out[b,c,i] = x[b,c,idx[i]], idx fixed (JAX threefry seed 42 +
// sequential neighbor-swap scan), recomputed bit-exact on the HOST each call.
//
// R11: R9 structure (BAND=56, fused ATS idx delivery) + CHUNKED DMA PIPELINE:
// the Lc-row smem window is filled by 4 independent cp.async.bulk chunks
// (own mbarrier each); the unrolled gather loop waits only for the chunks it
// provably needs (host computes the exact per-iteration max window row and
// packs chunk requirements into a 2-bit-per-iteration uint param). Gather and
// fill overlap within each block, on top of 3-blocks/SM cross-block overlap.
// ---------------------------------------------------------------------------

#define GH 224
#define GW 224
#define HW (GH * GW)          // 50176
#define NPLANES 384           // 128 * 3
#define BAND 56
#define NBANDS (GH / BAND)    // 4
#define BANDW (BAND * GW)     // 12544
#define BANDW4 (BANDW / 4)    // 3136
#define NT 512
#define GITER ((BANDW4 + NT - 1) / NT)   // 7
#define NCHK 4                // DMA chunks per window
#define HW16 (HW / 8)
#define NCOPY 16
#define CHUNK16 (HW16 / NCOPY)

__device__ unsigned short g_idxl[HW];
__device__ unsigned int g_flag[NCOPY];

static __device__ __forceinline__ uint32_t smem_u32(const void* p) {
    uint32_t a;
    asm("{ .reg .u64 t; cvta.to.shared.u64 t, %1; cvt.u32.u64 %0, t; }"
        : "=r"(a) : "l"(p));
    return a;
}
static __device__ __forceinline__ void mbar_init(uint32_t mb, uint32_t cnt) {
    asm volatile("mbarrier.init.shared.b64 [%0], %1;" :: "r"(mb), "r"(cnt)
                 : "memory");
}
static __device__ __forceinline__ void mbar_expect_tx(uint32_t mb, uint32_t tx) {
    asm volatile("mbarrier.arrive.expect_tx.shared.b64 _, [%0], %1;"
                 :: "r"(mb), "r"(tx) : "memory");
}
static __device__ __forceinline__ void bulk_g2s(uint32_t dst, const void* src,
                                                uint32_t bytes, uint32_t mb) {
    asm volatile(
        "cp.async.bulk.shared::cluster.global.mbarrier::complete_tx::bytes "
        "[%0], [%1], %2, [%3];"
        :: "r"(dst), "l"(src), "r"(bytes), "r"(mb) : "memory");
}
static __device__ __forceinline__ void mbar_wait(uint32_t mb, uint32_t phase) {
    asm volatile(
        "{\n\t"
        ".reg .pred P;\n\t"
        "WAIT_%=: \n\t"
        "mbarrier.try_wait.parity.acquire.cta.shared::cta.b64 P, [%0], %1, 0x989680;\n\t"
        "@P bra.uni DONE_%=;\n\t"
        "bra.uni WAIT_%=;\n\t"
        "DONE_%=: \n\t"
        "}"
        :: "r"(mb), "r"(phase) : "memory");
}
static __device__ __forceinline__ unsigned int ld_acquire(unsigned int* p) {
    unsigned int v;
    asm volatile("ld.global.acquire.gpu.u32 %0, [%1];" : "=r"(v) : "l"(p)
                 : "memory");
    return v;
}

// ---- fused banded gather, chunk-pipelined fill, window height Lc -----------
template <int Lc>
__global__ __launch_bounds__(NT)
void clop_band_t(const float* __restrict__ x, float* __restrict__ out,
                 const uint4* __restrict__ hidx, int do_copy,
                 unsigned int needpack) {
    extern __shared__ float sp[];                 // Lc*GW floats, row-major
    __shared__ __align__(8) unsigned long long mbar_s[NCHK];
    static_assert(Lc % NCHK == 0, "Lc divisible by chunk count");
    constexpr int CR = Lc / NCHK;                 // rows per chunk
    constexpr uint32_t CB = (uint32_t)CR * GW * sizeof(float);

    const int plane = blockIdx.x;
    const int band  = blockIdx.y;
    const float* src = x + (size_t)plane * HW;

    int ws = band * BAND - ((Lc - BAND) >> 1);    // toroidal window start row
    if (ws < 0) ws += GH;

    const uint32_t mb0 = smem_u32(&mbar_s[0]);
    if (threadIdx.x == 0) {
#pragma unroll
        for (int c = 0; c < NCHK; c++) mbar_init(mb0 + 8 * c, 1);
    }
    __syncthreads();

    // (1) issue all 4 chunk DMAs (each may wrap the plane boundary once)
    if (threadIdx.x == 0) {
#pragma unroll
        for (int c = 0; c < NCHK; c++) {
            const uint32_t mb = mb0 + 8 * c;
            mbar_expect_tx(mb, CB);
            int gr0 = ws + c * CR;
            if (gr0 >= GH) gr0 -= GH;
            const int n1 = (GH - gr0 < CR) ? (GH - gr0) : CR;
            const uint32_t b1 = (uint32_t)n1 * GW * sizeof(float);
            const uint32_t sdst = smem_u32(sp) + (uint32_t)c * CB;
            bulk_g2s(sdst, src + (size_t)gr0 * GW, b1, mb);
            if (n1 < CR) bulk_g2s(sdst + b1, src, CB - b1, mb);
        }
    }

    // (2) copier role: first NCOPY scheduled blocks ship idx chunks (ATS)
    if (do_copy) {
        const int bid = blockIdx.y * gridDim.x + blockIdx.x;
        if (bid < NCOPY) {
            const int base16 = bid * CHUNK16;
            if (threadIdx.x < CHUNK16) {
                reinterpret_cast<uint4*>(g_idxl)[base16 + threadIdx.x] =
                    __ldg(&hidx[base16 + threadIdx.x]);
            }
            __syncthreads();
            if (threadIdx.x == 0) {
                __threadfence();
                atomicExch(&g_flag[bid], 1u);
            }
        }
        if (threadIdx.x < NCOPY) {
            while (ld_acquire(&g_flag[threadIdx.x]) == 0u) __nanosleep(64);
        }
        __syncthreads();
    }

    // (3) prefetch idx into registers (independent of window DMA)
    const size_t base = (size_t)band * BANDW;
    const ushort4* id4 = reinterpret_cast<const ushort4*>(g_idxl + base);
    ushort4 idbuf[GITER];
#pragma unroll
    for (int u = 0; u < GITER; u++) {
        const int k = threadIdx.x + u * NT;
        if (k < BANDW4) idbuf[u] = __ldg(&id4[k]);
    }

    // (4) pipelined gather: wait only for the chunks iteration u needs
    float4* dst = reinterpret_cast<float4*>(out + (size_t)plane * HW + base);
    int waited = -1;   // highest chunk index already waited on
#pragma unroll
    for (int u = 0; u < GITER; u++) {
        const int need = (int)((needpack >> (2 * u)) & 3u);
        while (waited < need) {
            waited++;
            mbar_wait(mb0 + 8 * waited, 0);
        }
        const int k = threadIdx.x + u * NT;
        if (k < BANDW4) {
            const ushort4 id = idbuf[u];
            float4 v;
            v.x = sp[id.x];
            v.y = sp[id.y];
            v.z = sp[id.z];
            v.w = sp[id.w];
            __stcs(&dst[k], v);
        }
    }
}

// ---------------------------------------------------------------------------
// Host-side exact replication of the JAX RNG pipeline (partitionable threefry)
// ---------------------------------------------------------------------------

static inline uint32_t rotl32(uint32_t x, int d) {
    return (x << d) | (x >> (32 - d));
}

struct TFKey { uint32_t hi, lo; };

static void threefry2x32(uint32_t k0, uint32_t k1, uint32_t x0, uint32_t x1,
                         uint32_t* o0, uint32_t* o1) {
    const uint32_t ks0 = k0, ks1 = k1, ks2 = k0 ^ k1 ^ 0x1BD11BDAu;
    static const int ra[4] = {13, 15, 26, 6};
    static const int rb[4] = {17, 29, 16, 24};
    x0 += ks0; x1 += ks1;
    for (int i = 0; i < 4; i++) { x0 += x1; x1 = rotl32(x1, ra[i]); x1 ^= x0; }
    x0 += ks1; x1 += ks2 + 1u;
    for (int i = 0; i < 4; i++) { x0 += x1; x1 = rotl32(x1, rb[i]); x1 ^= x0; }
    x0 += ks2; x1 += ks0 + 2u;
    for (int i = 0; i < 4; i++) { x0 += x1; x1 = rotl32(x1, ra[i]); x1 ^= x0; }
    x0 += ks0; x1 += ks1 + 3u;
    for (int i = 0; i < 4; i++) { x0 += x1; x1 = rotl32(x1, rb[i]); x1 ^= x0; }
    x0 += ks1; x1 += ks2 + 4u;
    for (int i = 0; i < 4; i++) { x0 += x1; x1 = rotl32(x1, ra[i]); x1 ^= x0; }
    x0 += ks2; x1 += ks0 + 5u;
    *o0 = x0; *o1 = x1;
}

static inline TFKey tf_child(TFKey k, uint32_t j) {
    TFKey r; threefry2x32(k.hi, k.lo, 0u, j, &r.hi, &r.lo); return r;
}
static inline uint32_t tf_bits32(TFKey k, uint32_t i) {
    uint32_t a, b; threefry2x32(k.hi, k.lo, 0u, i, &a, &b); return a ^ b;
}

static void compute_host_idx(int* h_idx) {
    const int n = HW;
    TFKey key42 = {0u, 42u};
    TFKey k1 = tf_child(key42, 0u);
    TFKey k2 = tf_child(key42, 1u);

    std::vector<int> order(n);
    for (int i = 0; i < n; i++) order[i] = i;
    {
        TFKey cur = k1;
        std::vector<uint64_t> kv(n);
        std::vector<int> nx(n);
        for (int round = 0; round < 2; round++) {
            TFKey nkey = tf_child(cur, 0u);
            TFKey sub  = tf_child(cur, 1u);
            for (int i = 0; i < n; i++)
                kv[(size_t)i] = ((uint64_t)tf_bits32(sub, (uint32_t)i) << 32) |
                                (uint32_t)i;
            std::sort(kv.begin(), kv.end());
            for (int j = 0; j < n; j++)
                nx[(size_t)j] = order[(size_t)(uint32_t)kv[(size_t)j]];
            order.swap(nx);
            cur = nkey;
        }
    }

    float p0 = (float)(1.0 - 0.3), pq = (float)(0.3 / 4.0);
    float c[5];
    c[0] = p0;
    for (int j = 1; j < 5; j++) c[j] = c[j - 1] + pq;

    std::vector<uint8_t> rs(n);
    for (int i = 0; i < n; i++) {
        uint32_t bits = tf_bits32(k2, (uint32_t)i);
        uint32_t fb = (bits >> 9) | 0x3F800000u;
        float f; std::memcpy(&f, &fb, 4);
        f -= 1.0f;
        float r = c[4] * (1.0f - f);
        int ind = 0;
        while (ind < 5 && c[ind] < r) ind++;
        rs[(size_t)i] = (uint8_t)ind;
    }

    for (int i = 0; i < n; i++) h_idx[i] = i;
    for (int t = 0; t < n; t++) {
        const int a = order[(size_t)t];
        const int r = rs[(size_t)t];
        const int i = a / GW, j = a % GW;
        const int ii = (r == 1) ? (i + 1) % GH : (r == 2) ? (i + GH - 1) % GH : i;
        const int jj = (r == 3) ? (j + 1) % GW : (r == 4) ? (j + GW - 1) % GW : j;
        const int b = (r == 0) ? a : (ii * GW + jj);
        const int va = h_idx[a], vb = h_idx[b];
        h_idx[a] = vb; h_idx[b] = va;
    }
}

// ---------------------------------------------------------------------------

template <int Lc>
static void launch_band(const float* x, float* out, const uint4* hidx,
                        int do_copy, unsigned int needpack) {
    const int smem = Lc * GW * (int)sizeof(float);
    cudaFuncSetAttribute(clop_band_t<Lc>,
                         cudaFuncAttributeMaxDynamicSharedMemorySize, smem);
    dim3 grid(NPLANES, NBANDS);
    clop_band_t<Lc><<<grid, NT, smem>>>(x, out, hidx, do_copy, needpack);
}

extern "C" void kernel_launch(void* const* d_in, const int* in_sizes, int n_in,
                              void* d_out, int out_size) {
    (void)in_sizes; (void)n_in; (void)out_size;

    static int h_idx[HW];
    alignas(16) static unsigned short h_idxl[HW];   // ATS-read by the kernel
    compute_host_idx(h_idx);

    // max toroidal row distance from each output row's band window
    int D = 0;
    for (int i = 0; i < HW; i++) {
        const int r_out = i / GW;
        const int bandstart = (r_out / BAND) * BAND;
        const int r_src = h_idx[i] / GW;
        int dist = 0;
        if (r_src >= bandstart && r_src < bandstart + BAND) {
            dist = 0;
        } else {
            int dlo = (bandstart - r_src + GH) % GH;
            int dhi = (r_src - (bandstart + BAND - 1) + GH) % GH;
            dist = dlo < dhi ? dlo : dhi;
        }
        if (dist > D) D = dist;
    }

    // window heights (divisible by NCHK=4): L = BAND + 2*Dp padded up
    int Lc;
    if (D <= 2)       Lc = 60;
    else if (D <= 6)  Lc = 68;
    else if (D <= 10) Lc = 76;
    else if (D <= 18) Lc = 92;
    else              Lc = 224;

    // window-relative row-major indices + exact per-iteration chunk needs
    const int Dp = (Lc - BAND) / 2;
    const int CR = Lc / NCHK;
    int maxt[GITER];
    for (int u = 0; u < GITER; u++) maxt[u] = 0;
    for (int i = 0; i < HW; i++) {
        const int r_out = i / GW;
        const int ws0 = (r_out / BAND) * BAND - Dp;
        const int r_src = h_idx[i] / GW;
        const int c_src = h_idx[i] % GW;
        int t = r_src - ws0;
        t %= GH; if (t < 0) t += GH;
        h_idxl[i] = (unsigned short)(t * GW + c_src);
        // iteration index of this output element within its band
        const int kk = (i / 4) % BANDW4;      // float4 index within band
        const int u = kk / NT;
        if (t > maxt[u]) maxt[u] = t;
    }
    unsigned int needpack = 0;
    for (int u = 0; u < GITER; u++) {
        unsigned int need = (unsigned int)(maxt[u] / CR);
        if (need > 3u) need = 3u;
        needpack |= need << (2 * u);
    }

    int ats = 0;
    cudaDeviceGetAttribute(&ats, cudaDevAttrPageableMemoryAccess, 0);

    const float* x = (const float*)d_in[0];
    float* out = (float*)d_out;
    const uint4* hidx = reinterpret_cast<const uint4*>(h_idxl);

    if (!ats) {
        cudaMemcpyToSymbolAsync(g_idxl, h_idxl, sizeof(h_idxl), 0,
                                cudaMemcpyHostToDevice, 0);
    }
    const int do_copy = ats ? 1 : 0;

    if (Lc == 60)      launch_band<60>(x, out, hidx, do_copy, needpack);
    else if (Lc == 68) launch_band<68>(x, out, hidx, do_copy, needpack);
    else if (Lc == 76) launch_band<76>(x, out, hidx, do_copy, needpack);
    else if (Lc == 92) launch_band<92>(x, out, hidx, do_copy, needpack);
    else               launch_band<224>(x, out, hidx, do_copy, needpack);
}

// round 12
// speedup vs baseline: 1.1130x; 1.0581x over previous
#include <cuda_runtime.h>
#include <cstdint>
#include <cstring>
#include <vector>
#include <algorithm>

// ---------------------------------------------------------------------------
// CLOPLayer: out[b,c,i] = x[b,c,idx[i]], idx fixed (JAX threefry seed 42 +
// sequential neighbor-swap scan), recomputed bit-exact on the HOST each call.
//
// R12: R9 kernel (BAND=56, single window DMA, fused ATS idx delivery) with a
// finer window ladder: Lc=60 (D<=2) / Lc=64 (D<=4) fit FOUR 512-thread blocks
// per SM (smem 4*Lc*896 <= 233472, regs forced <=32 via launch_bounds(512,4),
// 64 warps) -> +33% concurrent fill/drain pipelines vs the 3-block Lc=68
// config. R11 showed the kernel is serialization-bound, not DRAM-bound
// (actual DRAM traffic ~104MB; halo reads hit L2), so concurrency is the
// lever. Falls back to Lc=68/76/92/224 for larger D (R9-identical).
// ---------------------------------------------------------------------------

#define GH 224
#define GW 224
#define HW (GH * GW)          // 50176
#define NPLANES 384           // 128 * 3
#define BAND 56
#define NBANDS (GH / BAND)    // 4
#define BANDW (BAND * GW)     // 12544
#define BANDW4 (BANDW / 4)    // 3136
#define NT 512
#define GITER ((BANDW4 + NT - 1) / NT)   // 7
#define HW16 (HW / 8)
#define NCOPY 16
#define CHUNK16 (HW16 / NCOPY)  // 392

__device__ unsigned short g_idxl[HW];
__device__ unsigned int g_flag[NCOPY];

static __device__ __forceinline__ uint32_t smem_u32(const void* p) {
    uint32_t a;
    asm("{ .reg .u64 t; cvta.to.shared.u64 t, %1; cvt.u32.u64 %0, t; }"
        : "=r"(a) : "l"(p));
    return a;
}
static __device__ __forceinline__ void mbar_init(uint32_t mb, uint32_t cnt) {
    asm volatile("mbarrier.init.shared.b64 [%0], %1;" :: "r"(mb), "r"(cnt)
                 : "memory");
}
static __device__ __forceinline__ void mbar_expect_tx(uint32_t mb, uint32_t tx) {
    asm volatile("mbarrier.arrive.expect_tx.shared.b64 _, [%0], %1;"
                 :: "r"(mb), "r"(tx) : "memory");
}
static __device__ __forceinline__ void bulk_g2s(uint32_t dst, const void* src,
                                                uint32_t bytes, uint32_t mb) {
    asm volatile(
        "cp.async.bulk.shared::cluster.global.mbarrier::complete_tx::bytes "
        "[%0], [%1], %2, [%3];"
        :: "r"(dst), "l"(src), "r"(bytes), "r"(mb) : "memory");
}
static __device__ __forceinline__ void mbar_wait(uint32_t mb, uint32_t phase) {
    asm volatile(
        "{\n\t"
        ".reg .pred P;\n\t"
        "WAIT_%=: \n\t"
        "mbarrier.try_wait.parity.acquire.cta.shared::cta.b64 P, [%0], %1, 0x989680;\n\t"
        "@P bra.uni DONE_%=;\n\t"
        "bra.uni WAIT_%=;\n\t"
        "DONE_%=: \n\t"
        "}"
        :: "r"(mb), "r"(phase) : "memory");
}
static __device__ __forceinline__ unsigned int ld_acquire(unsigned int* p) {
    unsigned int v;
    asm volatile("ld.global.acquire.gpu.u32 %0, [%1];" : "=r"(v) : "l"(p)
                 : "memory");
    return v;
}

// ---- fused banded gather + idx delivery, compile-time window height Lc -----
template <int Lc>
__global__ __launch_bounds__(NT, 4)
void clop_band_t(const float* __restrict__ x, float* __restrict__ out,
                 const uint4* __restrict__ hidx, int do_copy) {
    extern __shared__ float sp[];                 // Lc*GW floats, row-major
    __shared__ __align__(8) unsigned long long mbar_s;

    const int plane = blockIdx.x;
    const int band  = blockIdx.y;
    const float* src = x + (size_t)plane * HW;

    int ws = band * BAND - ((Lc - BAND) >> 1);    // toroidal window start row
    if (ws < 0) ws += GH;

    const uint32_t mb = smem_u32(&mbar_s);
    if (threadIdx.x == 0) mbar_init(mb, 1);
    __syncthreads();

    // (1) x-window DMA first — independent of idx
    if (threadIdx.x == 0) {
        constexpr uint32_t TOTAL = (uint32_t)Lc * GW * sizeof(float);
        mbar_expect_tx(mb, TOTAL);
        const int n1 = (GH - ws < Lc) ? (GH - ws) : Lc;   // rows before wrap
        const uint32_t b1 = (uint32_t)n1 * GW * sizeof(float);
        bulk_g2s(smem_u32(sp), src + (size_t)ws * GW, b1, mb);
        if (n1 < Lc) {
            bulk_g2s(smem_u32(sp) + b1, src, TOTAL - b1, mb);
        }
    }

    // (2) copier role: first NCOPY scheduled blocks ship idx chunks (ATS)
    if (do_copy) {
        const int bid = blockIdx.y * gridDim.x + blockIdx.x;
        if (bid < NCOPY) {
            const int base16 = bid * CHUNK16;
            if (threadIdx.x < CHUNK16) {
                reinterpret_cast<uint4*>(g_idxl)[base16 + threadIdx.x] =
                    __ldg(&hidx[base16 + threadIdx.x]);
            }
            __syncthreads();
            if (threadIdx.x == 0) {
                __threadfence();
                atomicExch(&g_flag[bid], 1u);
            }
        }
        if (threadIdx.x < NCOPY) {
            while (ld_acquire(&g_flag[threadIdx.x]) == 0u) __nanosleep(64);
        }
        __syncthreads();
    }

    // (3) prefetch idx for this band into registers, then DMA wait
    const size_t base = (size_t)band * BANDW;
    const ushort4* id4 = reinterpret_cast<const ushort4*>(g_idxl + base);
    ushort4 idbuf[GITER];
#pragma unroll
    for (int u = 0; u < GITER; u++) {
        const int k = threadIdx.x + u * NT;
        if (k < BANDW4) idbuf[u] = __ldg(&id4[k]);
    }

    mbar_wait(mb, 0);

    // (4) gather + coalesced float4 stores
    float4* dst = reinterpret_cast<float4*>(out + (size_t)plane * HW + base);
#pragma unroll
    for (int u = 0; u < GITER; u++) {
        const int k = threadIdx.x + u * NT;
        if (k < BANDW4) {
            const ushort4 id = idbuf[u];
            float4 v;
            v.x = sp[id.x];
            v.y = sp[id.y];
            v.z = sp[id.z];
            v.w = sp[id.w];
            __stcs(&dst[k], v);
        }
    }
}

// ---------------------------------------------------------------------------
// Host-side exact replication of the JAX RNG pipeline (partitionable threefry)
// ---------------------------------------------------------------------------

static inline uint32_t rotl32(uint32_t x, int d) {
    return (x << d) | (x >> (32 - d));
}

struct TFKey { uint32_t hi, lo; };

static void threefry2x32(uint32_t k0, uint32_t k1, uint32_t x0, uint32_t x1,
                         uint32_t* o0, uint32_t* o1) {
    const uint32_t ks0 = k0, ks1 = k1, ks2 = k0 ^ k1 ^ 0x1BD11BDAu;
    static const int ra[4] = {13, 15, 26, 6};
    static const int rb[4] = {17, 29, 16, 24};
    x0 += ks0; x1 += ks1;
    for (int i = 0; i < 4; i++) { x0 += x1; x1 = rotl32(x1, ra[i]); x1 ^= x0; }
    x0 += ks1; x1 += ks2 + 1u;
    for (int i = 0; i < 4; i++) { x0 += x1; x1 = rotl32(x1, rb[i]); x1 ^= x0; }
    x0 += ks2; x1 += ks0 + 2u;
    for (int i = 0; i < 4; i++) { x0 += x1; x1 = rotl32(x1, ra[i]); x1 ^= x0; }
    x0 += ks0; x1 += ks1 + 3u;
    for (int i = 0; i < 4; i++) { x0 += x1; x1 = rotl32(x1, rb[i]); x1 ^= x0; }
    x0 += ks1; x1 += ks2 + 4u;
    for (int i = 0; i < 4; i++) { x0 += x1; x1 = rotl32(x1, ra[i]); x1 ^= x0; }
    x0 += ks2; x1 += ks0 + 5u;
    *o0 = x0; *o1 = x1;
}

static inline TFKey tf_child(TFKey k, uint32_t j) {
    TFKey r; threefry2x32(k.hi, k.lo, 0u, j, &r.hi, &r.lo); return r;
}
static inline uint32_t tf_bits32(TFKey k, uint32_t i) {
    uint32_t a, b; threefry2x32(k.hi, k.lo, 0u, i, &a, &b); return a ^ b;
}

static void compute_host_idx(int* h_idx) {
    const int n = HW;
    TFKey key42 = {0u, 42u};
    TFKey k1 = tf_child(key42, 0u);
    TFKey k2 = tf_child(key42, 1u);

    std::vector<int> order(n);
    for (int i = 0; i < n; i++) order[i] = i;
    {
        TFKey cur = k1;
        std::vector<uint64_t> kv(n);
        std::vector<int> nx(n);
        for (int round = 0; round < 2; round++) {
            TFKey nkey = tf_child(cur, 0u);
            TFKey sub  = tf_child(cur, 1u);
            for (int i = 0; i < n; i++)
                kv[(size_t)i] = ((uint64_t)tf_bits32(sub, (uint32_t)i) << 32) |
                                (uint32_t)i;
            std::sort(kv.begin(), kv.end());
            for (int j = 0; j < n; j++)
                nx[(size_t)j] = order[(size_t)(uint32_t)kv[(size_t)j]];
            order.swap(nx);
            cur = nkey;
        }
    }

    float p0 = (float)(1.0 - 0.3), pq = (float)(0.3 / 4.0);
    float c[5];
    c[0] = p0;
    for (int j = 1; j < 5; j++) c[j] = c[j - 1] + pq;

    std::vector<uint8_t> rs(n);
    for (int i = 0; i < n; i++) {
        uint32_t bits = tf_bits32(k2, (uint32_t)i);
        uint32_t fb = (bits >> 9) | 0x3F800000u;
        float f; std::memcpy(&f, &fb, 4);
        f -= 1.0f;
        float r = c[4] * (1.0f - f);
        int ind = 0;
        while (ind < 5 && c[ind] < r) ind++;
        rs[(size_t)i] = (uint8_t)ind;
    }

    for (int i = 0; i < n; i++) h_idx[i] = i;
    for (int t = 0; t < n; t++) {
        const int a = order[(size_t)t];
        const int r = rs[(size_t)t];
        const int i = a / GW, j = a % GW;
        const int ii = (r == 1) ? (i + 1) % GH : (r == 2) ? (i + GH - 1) % GH : i;
        const int jj = (r == 3) ? (j + 1) % GW : (r == 4) ? (j + GW - 1) % GW : j;
        const int b = (r == 0) ? a : (ii * GW + jj);
        const int va = h_idx[a], vb = h_idx[b];
        h_idx[a] = vb; h_idx[b] = va;
    }
}

// ---------------------------------------------------------------------------

template <int Lc>
static void launch_band(const float* x, float* out, const uint4* hidx,
                        int do_copy) {
    const int smem = Lc * GW * (int)sizeof(float);
    cudaFuncSetAttribute(clop_band_t<Lc>,
                         cudaFuncAttributeMaxDynamicSharedMemorySize, smem);
    dim3 grid(NPLANES, NBANDS);
    clop_band_t<Lc><<<grid, NT, smem>>>(x, out, hidx, do_copy);
}

extern "C" void kernel_launch(void* const* d_in, const int* in_sizes, int n_in,
                              void* d_out, int out_size) {
    (void)in_sizes; (void)n_in; (void)out_size;

    static int h_idx[HW];
    alignas(16) static unsigned short h_idxl[HW];   // ATS-read by the kernel
    compute_host_idx(h_idx);

    // max toroidal row distance from each output row's band window
    int D = 0;
    for (int i = 0; i < HW; i++) {
        const int r_out = i / GW;
        const int bandstart = (r_out / BAND) * BAND;
        const int r_src = h_idx[i] / GW;
        int dist = 0;
        if (r_src >= bandstart && r_src < bandstart + BAND) {
            dist = 0;
        } else {
            int dlo = (bandstart - r_src + GH) % GH;
            int dhi = (r_src - (bandstart + BAND - 1) + GH) % GH;
            dist = dlo < dhi ? dlo : dhi;
        }
        if (dist > D) D = dist;
    }

    // window ladder: Lc<=64 -> 4 blocks/SM; else R9-identical 3-block configs
    int Lc;
    if (D <= 2)       Lc = 60;
    else if (D <= 4)  Lc = 64;
    else if (D <= 6)  Lc = 68;
    else if (D <= 10) Lc = 76;
    else if (D <= 18) Lc = 92;
    else              Lc = 224;

    // window-relative row-major indices for the padded window
    const int Dp = (Lc - BAND) / 2;
    for (int i = 0; i < HW; i++) {
        const int r_out = i / GW;
        const int ws0 = (r_out / BAND) * BAND - Dp;
        const int r_src = h_idx[i] / GW;
        const int c_src = h_idx[i] % GW;
        int t = r_src - ws0;
        t %= GH; if (t < 0) t += GH;
        h_idxl[i] = (unsigned short)(t * GW + c_src);
    }

    int ats = 0;
    cudaDeviceGetAttribute(&ats, cudaDevAttrPageableMemoryAccess, 0);

    const float* x = (const float*)d_in[0];
    float* out = (float*)d_out;
    const uint4* hidx = reinterpret_cast<const uint4*>(h_idxl);

    if (!ats) {
        cudaMemcpyToSymbolAsync(g_idxl, h_idxl, sizeof(h_idxl), 0,
                                cudaMemcpyHostToDevice, 0);
    }
    const int do_copy = ats ? 1 : 0;

    if (Lc == 60)      launch_band<60>(x, out, hidx, do_copy);
    else if (Lc == 64) launch_band<64>(x, out, hidx, do_copy);
    else if (Lc == 68) launch_band<68>(x, out, hidx, do_copy);
    else if (Lc == 76) launch_band<76>(x, out, hidx, do_copy);
    else if (Lc == 92) launch_band<92>(x, out, hidx, do_copy);
    else               launch_band<224>(x, out, hidx, do_copy);
}

// round 13
// speedup vs baseline: 1.1239x; 1.0098x over previous
#include <cuda_runtime.h>
#include <cstdint>
#include <cstring>
#include <vector>
#include <algorithm>

// ---------------------------------------------------------------------------
// CLOPLayer: out[b,c,i] = x[b,c,idx[i]], idx fixed (JAX threefry seed 42 +
// sequential neighbor-swap scan), recomputed bit-exact on the HOST each call.
//
// R13: PERSISTENT DOUBLE-BUFFERED pipeline. 444 blocks (1 wave, 3/SM), each
// loops over ~7 (plane,band) tiles (BAND=28, 3072 tiles). Two smem windows +
// two mbarriers: while gathering tile i from buf i&1, the DMA for tile i+1
// is already streaming into the other buffer -> fill and drain overlap in
// steady state instead of serializing once per short-lived block (the R9-R12
// bottleneck). Buffer parity = (i>>1)&1, stateless. Fused ATS idx delivery
// (GB300 C2C) kept: first 16 blocks copy the uint16 idx table, others spin
// once on flags before the tile loop. Replay-deterministic throughout.
// ---------------------------------------------------------------------------

#define GH 224
#define GW 224
#define HW (GH * GW)            // 50176
#define HW4 (HW / 4)
#define NPLANES 384             // 128 * 3
#define BAND 28
#define NBANDS (GH / BAND)      // 8
#define BANDW (BAND * GW)       // 6272
#define BANDW4 (BANDW / 4)      // 1568
#define TILES (NPLANES * NBANDS) // 3072
#define NT 512
#define GITER ((BANDW4 + NT - 1) / NT)   // 4 (last partial: 1568=3*512+32)
#define HW16 (HW / 8)
#define NCOPY 16
#define CHUNK16 (HW16 / NCOPY)  // 392

__device__ unsigned short g_idxl[HW];
__device__ unsigned int g_flag[NCOPY];
__device__ int g_idx[HW];       // absolute idx (degenerate fallback)

static __device__ __forceinline__ uint32_t smem_u32(const void* p) {
    uint32_t a;
    asm("{ .reg .u64 t; cvta.to.shared.u64 t, %1; cvt.u32.u64 %0, t; }"
        : "=r"(a) : "l"(p));
    return a;
}
static __device__ __forceinline__ void mbar_init(uint32_t mb, uint32_t cnt) {
    asm volatile("mbarrier.init.shared.b64 [%0], %1;" :: "r"(mb), "r"(cnt)
                 : "memory");
}
static __device__ __forceinline__ void mbar_expect_tx(uint32_t mb, uint32_t tx) {
    asm volatile("mbarrier.arrive.expect_tx.shared.b64 _, [%0], %1;"
                 :: "r"(mb), "r"(tx) : "memory");
}
static __device__ __forceinline__ void bulk_g2s(uint32_t dst, const void* src,
                                                uint32_t bytes, uint32_t mb) {
    asm volatile(
        "cp.async.bulk.shared::cluster.global.mbarrier::complete_tx::bytes "
        "[%0], [%1], %2, [%3];"
        :: "r"(dst), "l"(src), "r"(bytes), "r"(mb) : "memory");
}
static __device__ __forceinline__ void mbar_wait(uint32_t mb, uint32_t phase) {
    asm volatile(
        "{\n\t"
        ".reg .pred P;\n\t"
        "WAIT_%=: \n\t"
        "mbarrier.try_wait.parity.acquire.cta.shared::cta.b64 P, [%0], %1, 0x989680;\n\t"
        "@P bra.uni DONE_%=;\n\t"
        "bra.uni WAIT_%=;\n\t"
        "DONE_%=: \n\t"
        "}"
        :: "r"(mb), "r"(phase) : "memory");
}
static __device__ __forceinline__ unsigned int ld_acquire(unsigned int* p) {
    unsigned int v;
    asm volatile("ld.global.acquire.gpu.u32 %0, [%1];" : "=r"(v) : "l"(p)
                 : "memory");
    return v;
}

// ---- persistent double-buffered gather, window height Lc --------------------
template <int Lc>
__global__ __launch_bounds__(NT, 3)
void clop_pers(const float* __restrict__ x, float* __restrict__ out,
               const uint4* __restrict__ hidx, int do_copy) {
    extern __shared__ float sp[];                 // 2 * Lc*GW floats
    __shared__ __align__(8) unsigned long long mbar_s[2];
    constexpr uint32_t WBYTES = (uint32_t)Lc * GW * sizeof(float);

    const uint32_t mb0 = smem_u32(&mbar_s[0]);
    if (threadIdx.x == 0) { mbar_init(mb0, 1); mbar_init(mb0 + 8, 1); }
    __syncthreads();

    const uint32_t sbase = smem_u32(sp);

    // stage(tile, buf): issue expect_tx + 1-2 bulk copies for that window
    auto stage = [&](int tile, int buf) {
        const int plane = tile >> 3;              // NBANDS == 8
        const int band  = tile & 7;
        const float* src = x + (size_t)plane * HW;
        int ws = band * BAND - ((Lc - BAND) >> 1);
        if (ws < 0) ws += GH;
        const uint32_t mb = mb0 + 8 * buf;
        mbar_expect_tx(mb, WBYTES);
        const int n1 = (GH - ws < Lc) ? (GH - ws) : Lc;
        const uint32_t b1 = (uint32_t)n1 * GW * sizeof(float);
        const uint32_t sdst = sbase + (uint32_t)buf * WBYTES;
        bulk_g2s(sdst, src + (size_t)ws * GW, b1, mb);
        if (n1 < Lc) bulk_g2s(sdst + b1, src, WBYTES - b1, mb);
    };

    // prologue: first tile's DMA
    const int t0 = blockIdx.x;
    if (threadIdx.x == 0 && t0 < TILES) stage(t0, 0);

    // fused idx delivery (ATS): copiers write chunks, everyone spins once
    if (do_copy) {
        if (blockIdx.x < NCOPY) {
            const int base16 = blockIdx.x * CHUNK16;
            if (threadIdx.x < CHUNK16) {
                reinterpret_cast<uint4*>(g_idxl)[base16 + threadIdx.x] =
                    __ldg(&hidx[base16 + threadIdx.x]);
            }
            __syncthreads();
            if (threadIdx.x == 0) {
                __threadfence();
                atomicExch(&g_flag[blockIdx.x], 1u);
            }
        }
        if (threadIdx.x < NCOPY) {
            while (ld_acquire(&g_flag[threadIdx.x]) == 0u) __nanosleep(64);
        }
        __syncthreads();
    }

    // steady-state tile loop
    int i = 0;
    for (int t = t0; t < TILES; t += gridDim.x, i++) {
        const int b = i & 1;
        // issue next tile's DMA into the other buffer (freed by the
        // __syncthreads at the end of the previous iteration)
        if (threadIdx.x == 0 && t + (int)gridDim.x < TILES) {
            stage(t + gridDim.x, b ^ 1);
        }

        // prefetch idx for this tile (L2-hot) while DMA streams
        const int plane = t >> 3;
        const int band  = t & 7;
        const size_t base = (size_t)band * BANDW;
        const ushort4* id4 = reinterpret_cast<const ushort4*>(g_idxl + base);
        ushort4 idbuf[GITER];
#pragma unroll
        for (int u = 0; u < GITER; u++) {
            const int k = threadIdx.x + u * NT;
            if (k < BANDW4) idbuf[u] = __ldg(&id4[k]);
        }

        mbar_wait(mb0 + 8 * b, (i >> 1) & 1);

        const float* w = sp + (size_t)b * (WBYTES / sizeof(float));
        float4* dst = reinterpret_cast<float4*>(out + (size_t)plane * HW + base);
#pragma unroll
        for (int u = 0; u < GITER; u++) {
            const int k = threadIdx.x + u * NT;
            if (k < BANDW4) {
                const ushort4 id = idbuf[u];
                float4 v;
                v.x = w[id.x];
                v.y = w[id.y];
                v.z = w[id.z];
                v.w = w[id.w];
                __stcs(&dst[k], v);
            }
        }
        __syncthreads();   // all warps done reading buf b -> reusable
    }
}

// ---- degenerate fallback: full-plane gather (R1) ----------------------------
__global__ __launch_bounds__(1024, 1)
void clop_gather(const float* __restrict__ x, float* __restrict__ out) {
    extern __shared__ float sp[];
    const size_t off = (size_t)blockIdx.x * HW;
    const float4* src = reinterpret_cast<const float4*>(x + off);
    float4* sp4 = reinterpret_cast<float4*>(sp);
    for (int k = threadIdx.x; k < HW4; k += 1024) sp4[k] = src[k];
    __syncthreads();
    float4* dst = reinterpret_cast<float4*>(out + off);
    const int4* idx4 = reinterpret_cast<const int4*>(g_idx);
    for (int k = threadIdx.x; k < HW4; k += 1024) {
        int4 id = __ldg(&idx4[k]);
        float4 v;
        v.x = sp[id.x]; v.y = sp[id.y]; v.z = sp[id.z]; v.w = sp[id.w];
        __stcs(&dst[k], v);
    }
}

// ---------------------------------------------------------------------------
// Host-side exact replication of the JAX RNG pipeline (partitionable threefry)
// ---------------------------------------------------------------------------

static inline uint32_t rotl32(uint32_t x, int d) {
    return (x << d) | (x >> (32 - d));
}

struct TFKey { uint32_t hi, lo; };

static void threefry2x32(uint32_t k0, uint32_t k1, uint32_t x0, uint32_t x1,
                         uint32_t* o0, uint32_t* o1) {
    const uint32_t ks0 = k0, ks1 = k1, ks2 = k0 ^ k1 ^ 0x1BD11BDAu;
    static const int ra[4] = {13, 15, 26, 6};
    static const int rb[4] = {17, 29, 16, 24};
    x0 += ks0; x1 += ks1;
    for (int i = 0; i < 4; i++) { x0 += x1; x1 = rotl32(x1, ra[i]); x1 ^= x0; }
    x0 += ks1; x1 += ks2 + 1u;
    for (int i = 0; i < 4; i++) { x0 += x1; x1 = rotl32(x1, rb[i]); x1 ^= x0; }
    x0 += ks2; x1 += ks0 + 2u;
    for (int i = 0; i < 4; i++) { x0 += x1; x1 = rotl32(x1, ra[i]); x1 ^= x0; }
    x0 += ks0; x1 += ks1 + 3u;
    for (int i = 0; i < 4; i++) { x0 += x1; x1 = rotl32(x1, rb[i]); x1 ^= x0; }
    x0 += ks1; x1 += ks2 + 4u;
    for (int i = 0; i < 4; i++) { x0 += x1; x1 = rotl32(x1, ra[i]); x1 ^= x0; }
    x0 += ks2; x1 += ks0 + 5u;
    *o0 = x0; *o1 = x1;
}

static inline TFKey tf_child(TFKey k, uint32_t j) {
    TFKey r; threefry2x32(k.hi, k.lo, 0u, j, &r.hi, &r.lo); return r;
}
static inline uint32_t tf_bits32(TFKey k, uint32_t i) {
    uint32_t a, b; threefry2x32(k.hi, k.lo, 0u, i, &a, &b); return a ^ b;
}

static void compute_host_idx(int* h_idx) {
    const int n = HW;
    TFKey key42 = {0u, 42u};
    TFKey k1 = tf_child(key42, 0u);
    TFKey k2 = tf_child(key42, 1u);

    std::vector<int> order(n);
    for (int i = 0; i < n; i++) order[i] = i;
    {
        TFKey cur = k1;
        std::vector<uint64_t> kv(n);
        std::vector<int> nx(n);
        for (int round = 0; round < 2; round++) {
            TFKey nkey = tf_child(cur, 0u);
            TFKey sub  = tf_child(cur, 1u);
            for (int i = 0; i < n; i++)
                kv[(size_t)i] = ((uint64_t)tf_bits32(sub, (uint32_t)i) << 32) |
                                (uint32_t)i;
            std::sort(kv.begin(), kv.end());
            for (int j = 0; j < n; j++)
                nx[(size_t)j] = order[(size_t)(uint32_t)kv[(size_t)j]];
            order.swap(nx);
            cur = nkey;
        }
    }

    float p0 = (float)(1.0 - 0.3), pq = (float)(0.3 / 4.0);
    float c[5];
    c[0] = p0;
    for (int j = 1; j < 5; j++) c[j] = c[j - 1] + pq;

    std::vector<uint8_t> rs(n);
    for (int i = 0; i < n; i++) {
        uint32_t bits = tf_bits32(k2, (uint32_t)i);
        uint32_t fb = (bits >> 9) | 0x3F800000u;
        float f; std::memcpy(&f, &fb, 4);
        f -= 1.0f;
        float r = c[4] * (1.0f - f);
        int ind = 0;
        while (ind < 5 && c[ind] < r) ind++;
        rs[(size_t)i] = (uint8_t)ind;
    }

    for (int i = 0; i < n; i++) h_idx[i] = i;
    for (int t = 0; t < n; t++) {
        const int a = order[(size_t)t];
        const int r = rs[(size_t)t];
        const int i = a / GW, j = a % GW;
        const int ii = (r == 1) ? (i + 1) % GH : (r == 2) ? (i + GH - 1) % GH : i;
        const int jj = (r == 3) ? (j + 1) % GW : (r == 4) ? (j + GW - 1) % GW : j;
        const int b = (r == 0) ? a : (ii * GW + jj);
        const int va = h_idx[a], vb = h_idx[b];
        h_idx[a] = vb; h_idx[b] = va;
    }
}

// ---------------------------------------------------------------------------

template <int Lc>
static void launch_pers(const float* x, float* out, const uint4* hidx,
                        int do_copy, int nblk) {
    const int smem = 2 * Lc * GW * (int)sizeof(float);
    cudaFuncSetAttribute(clop_pers<Lc>,
                         cudaFuncAttributeMaxDynamicSharedMemorySize, smem);
    clop_pers<Lc><<<nblk, NT, smem>>>(x, out, hidx, do_copy);
}

extern "C" void kernel_launch(void* const* d_in, const int* in_sizes, int n_in,
                              void* d_out, int out_size) {
    (void)in_sizes; (void)n_in; (void)out_size;

    static int h_idx[HW];
    alignas(16) static unsigned short h_idxl[HW];   // ATS-read by the kernel
    compute_host_idx(h_idx);

    // max toroidal row distance from each output row's band window
    int D = 0;
    for (int i = 0; i < HW; i++) {
        const int r_out = i / GW;
        const int bandstart = (r_out / BAND) * BAND;
        const int r_src = h_idx[i] / GW;
        int dist = 0;
        if (r_src >= bandstart && r_src < bandstart + BAND) {
            dist = 0;
        } else {
            int dlo = (bandstart - r_src + GH) % GH;
            int dhi = (r_src - (bandstart + BAND - 1) + GH) % GH;
            dist = dlo < dhi ? dlo : dhi;
        }
        if (dist > D) D = dist;
    }

    const float* x = (const float*)d_in[0];
    float* out = (float*)d_out;

    if (D > 18) {
        // degenerate fallback: full-plane gather with absolute idx memcpy
        cudaFuncSetAttribute(clop_gather,
                             cudaFuncAttributeMaxDynamicSharedMemorySize,
                             HW * (int)sizeof(float));
        cudaMemcpyToSymbolAsync(g_idx, h_idx, sizeof(h_idx), 0,
                                cudaMemcpyHostToDevice, 0);
        clop_gather<<<NPLANES, 1024, HW * sizeof(float)>>>(x, out);
        return;
    }

    // window ladder: 2 buffers of Lc rows; 3 blocks/SM needs 2*Lc*896 <= ~76KB
    int Lc, nblk;
    if (D <= 2)       { Lc = 32; nblk = 444; }
    else if (D <= 4)  { Lc = 36; nblk = 444; }
    else if (D <= 6)  { Lc = 40; nblk = 444; }
    else if (D <= 10) { Lc = 48; nblk = 296; }   // 2 blocks/SM
    else              { Lc = 64; nblk = 296; }

    // window-relative row-major indices for the padded window
    const int Dp = (Lc - BAND) / 2;
    for (int i = 0; i < HW; i++) {
        const int r_out = i / GW;
        const int ws0 = (r_out / BAND) * BAND - Dp;
        const int r_src = h_idx[i] / GW;
        const int c_src = h_idx[i] % GW;
        int t = r_src - ws0;
        t %= GH; if (t < 0) t += GH;
        h_idxl[i] = (unsigned short)(t * GW + c_src);
    }

    int ats = 0;
    cudaDeviceGetAttribute(&ats, cudaDevAttrPageableMemoryAccess, 0);
    const uint4* hidx = reinterpret_cast<const uint4*>(h_idxl);

    if (!ats) {
        cudaMemcpyToSymbolAsync(g_idxl, h_idxl, sizeof(h_idxl), 0,
                                cudaMemcpyHostToDevice, 0);
    }
    const int do_copy = ats ? 1 : 0;

    if (Lc == 32)      launch_pers<32>(x, out, hidx, do_copy, nblk);
    else if (Lc == 36) launch_pers<36>(x, out, hidx, do_copy, nblk);
    else if (Lc == 40) launch_pers<40>(x, out, hidx, do_copy, nblk);
    else if (Lc == 48) launch_pers<48>(x, out, hidx, do_copy, nblk);
    else               launch_pers<64>(x, out, hidx, do_copy, nblk);
}

// round 14
// speedup vs baseline: 1.1514x; 1.0245x over previous
#include <cuda_runtime.h>
#include <cstdint>
#include <cstring>
#include <vector>
#include <algorithm>

// ---------------------------------------------------------------------------
// CLOPLayer: out[b,c,i] = x[b,c,idx[i]], idx fixed (JAX threefry seed 42 +
// sequential neighbor-swap scan), recomputed bit-exact on the HOST each call.
//
// R14: persistent double-buffered pipeline (R13) at FULL thread occupancy:
// BAND=16, Lc=24 (D<=4), 512-thread blocks, smem 2*24*896=43KB -> FOUR
// blocks/SM (172KB of 227KB), 2048 threads = 64 warps/SM, 592 blocks over
// 5376 tiles (~9 tiles each, GITER=2). R12's 4-block attempt silently failed
// to fit (smem at the ceiling); this config fits with margin. Consecutive
// blocks process consecutive tiles -> adjacent windows share L2 halo.
// Fused ATS idx delivery (GB300 C2C) unchanged. Replay-deterministic.
// ---------------------------------------------------------------------------

#define GH 224
#define GW 224
#define HW (GH * GW)            // 50176
#define HW4 (HW / 4)
#define NPLANES 384             // 128 * 3
#define BAND 16
#define NBANDS (GH / BAND)      // 14
#define BANDW (BAND * GW)       // 3584
#define BANDW4 (BANDW / 4)      // 896
#define TILES (NPLANES * NBANDS) // 5376
#define NT 512
#define GITER 2                 // 896 = 512 + 384
#define HW16 (HW / 8)
#define NCOPY 16
#define CHUNK16 (HW16 / NCOPY)  // 392

__device__ unsigned short g_idxl[HW];
__device__ unsigned int g_flag[NCOPY];
__device__ int g_idx[HW];       // absolute idx (degenerate fallback)

static __device__ __forceinline__ uint32_t smem_u32(const void* p) {
    uint32_t a;
    asm("{ .reg .u64 t; cvta.to.shared.u64 t, %1; cvt.u32.u64 %0, t; }"
        : "=r"(a) : "l"(p));
    return a;
}
static __device__ __forceinline__ void mbar_init(uint32_t mb, uint32_t cnt) {
    asm volatile("mbarrier.init.shared.b64 [%0], %1;" :: "r"(mb), "r"(cnt)
                 : "memory");
}
static __device__ __forceinline__ void mbar_expect_tx(uint32_t mb, uint32_t tx) {
    asm volatile("mbarrier.arrive.expect_tx.shared.b64 _, [%0], %1;"
                 :: "r"(mb), "r"(tx) : "memory");
}
static __device__ __forceinline__ void bulk_g2s(uint32_t dst, const void* src,
                                                uint32_t bytes, uint32_t mb) {
    asm volatile(
        "cp.async.bulk.shared::cluster.global.mbarrier::complete_tx::bytes "
        "[%0], [%1], %2, [%3];"
        :: "r"(dst), "l"(src), "r"(bytes), "r"(mb) : "memory");
}
static __device__ __forceinline__ void mbar_wait(uint32_t mb, uint32_t phase) {
    asm volatile(
        "{\n\t"
        ".reg .pred P;\n\t"
        "WAIT_%=: \n\t"
        "mbarrier.try_wait.parity.acquire.cta.shared::cta.b64 P, [%0], %1, 0x989680;\n\t"
        "@P bra.uni DONE_%=;\n\t"
        "bra.uni WAIT_%=;\n\t"
        "DONE_%=: \n\t"
        "}"
        :: "r"(mb), "r"(phase) : "memory");
}
static __device__ __forceinline__ unsigned int ld_acquire(unsigned int* p) {
    unsigned int v;
    asm volatile("ld.global.acquire.gpu.u32 %0, [%1];" : "=r"(v) : "l"(p)
                 : "memory");
    return v;
}

// ---- persistent double-buffered gather, window height Lc --------------------
template <int Lc>
__global__ __launch_bounds__(NT, 4)
void clop_pers(const float* __restrict__ x, float* __restrict__ out,
               const uint4* __restrict__ hidx, int do_copy) {
    extern __shared__ float sp[];                 // 2 * Lc*GW floats
    __shared__ __align__(8) unsigned long long mbar_s[2];
    constexpr uint32_t WBYTES = (uint32_t)Lc * GW * sizeof(float);

    const uint32_t mb0 = smem_u32(&mbar_s[0]);
    if (threadIdx.x == 0) { mbar_init(mb0, 1); mbar_init(mb0 + 8, 1); }
    __syncthreads();

    const uint32_t sbase = smem_u32(sp);

    auto stage = [&](int tile, int buf) {
        const int plane = tile / NBANDS;
        const int band  = tile - plane * NBANDS;
        const float* src = x + (size_t)plane * HW;
        int ws = band * BAND - ((Lc - BAND) >> 1);
        if (ws < 0) ws += GH;
        const uint32_t mb = mb0 + 8 * buf;
        mbar_expect_tx(mb, WBYTES);
        const int n1 = (GH - ws < Lc) ? (GH - ws) : Lc;
        const uint32_t b1 = (uint32_t)n1 * GW * sizeof(float);
        const uint32_t sdst = sbase + (uint32_t)buf * WBYTES;
        bulk_g2s(sdst, src + (size_t)ws * GW, b1, mb);
        if (n1 < Lc) bulk_g2s(sdst + b1, src, WBYTES - b1, mb);
    };

    // prologue: first tile's DMA
    const int t0 = blockIdx.x;
    if (threadIdx.x == 0 && t0 < TILES) stage(t0, 0);

    // fused idx delivery (ATS): copiers write chunks, everyone spins once
    if (do_copy) {
        if (blockIdx.x < NCOPY) {
            const int base16 = blockIdx.x * CHUNK16;
            if (threadIdx.x < CHUNK16) {
                reinterpret_cast<uint4*>(g_idxl)[base16 + threadIdx.x] =
                    __ldg(&hidx[base16 + threadIdx.x]);
            }
            __syncthreads();
            if (threadIdx.x == 0) {
                __threadfence();
                atomicExch(&g_flag[blockIdx.x], 1u);
            }
        }
        if (threadIdx.x < NCOPY) {
            while (ld_acquire(&g_flag[threadIdx.x]) == 0u) __nanosleep(64);
        }
        __syncthreads();
    }

    // steady-state tile loop
    int i = 0;
    for (int t = t0; t < TILES; t += gridDim.x, i++) {
        const int b = i & 1;
        if (threadIdx.x == 0 && t + (int)gridDim.x < TILES) {
            stage(t + gridDim.x, b ^ 1);   // buffer freed by prev-iter sync
        }

        const int plane = t / NBANDS;
        const int band  = t - plane * NBANDS;
        const size_t base = (size_t)band * BANDW;
        const ushort4* id4 = reinterpret_cast<const ushort4*>(g_idxl + base);
        ushort4 idbuf[GITER];
#pragma unroll
        for (int u = 0; u < GITER; u++) {
            const int k = threadIdx.x + u * NT;
            if (k < BANDW4) idbuf[u] = __ldg(&id4[k]);
        }

        mbar_wait(mb0 + 8 * b, (i >> 1) & 1);

        const float* w = sp + (size_t)b * (WBYTES / sizeof(float));
        float4* dst = reinterpret_cast<float4*>(out + (size_t)plane * HW + base);
#pragma unroll
        for (int u = 0; u < GITER; u++) {
            const int k = threadIdx.x + u * NT;
            if (k < BANDW4) {
                const ushort4 id = idbuf[u];
                float4 v;
                v.x = w[id.x];
                v.y = w[id.y];
                v.z = w[id.z];
                v.w = w[id.w];
                __stcs(&dst[k], v);
            }
        }
        __syncthreads();   // all warps done reading buf b -> reusable
    }
}

// ---- degenerate fallback: full-plane gather (R1) ----------------------------
__global__ __launch_bounds__(1024, 1)
void clop_gather(const float* __restrict__ x, float* __restrict__ out) {
    extern __shared__ float sp[];
    const size_t off = (size_t)blockIdx.x * HW;
    const float4* src = reinterpret_cast<const float4*>(x + off);
    float4* sp4 = reinterpret_cast<float4*>(sp);
    for (int k = threadIdx.x; k < HW4; k += 1024) sp4[k] = src[k];
    __syncthreads();
    float4* dst = reinterpret_cast<float4*>(out + off);
    const int4* idx4 = reinterpret_cast<const int4*>(g_idx);
    for (int k = threadIdx.x; k < HW4; k += 1024) {
        int4 id = __ldg(&idx4[k]);
        float4 v;
        v.x = sp[id.x]; v.y = sp[id.y]; v.z = sp[id.z]; v.w = sp[id.w];
        __stcs(&dst[k], v);
    }
}

// ---------------------------------------------------------------------------
// Host-side exact replication of the JAX RNG pipeline (partitionable threefry)
// ---------------------------------------------------------------------------

static inline uint32_t rotl32(uint32_t x, int d) {
    return (x << d) | (x >> (32 - d));
}

struct TFKey { uint32_t hi, lo; };

static void threefry2x32(uint32_t k0, uint32_t k1, uint32_t x0, uint32_t x1,
                         uint32_t* o0, uint32_t* o1) {
    const uint32_t ks0 = k0, ks1 = k1, ks2 = k0 ^ k1 ^ 0x1BD11BDAu;
    static const int ra[4] = {13, 15, 26, 6};
    static const int rb[4] = {17, 29, 16, 24};
    x0 += ks0; x1 += ks1;
    for (int i = 0; i < 4; i++) { x0 += x1; x1 = rotl32(x1, ra[i]); x1 ^= x0; }
    x0 += ks1; x1 += ks2 + 1u;
    for (int i = 0; i < 4; i++) { x0 += x1; x1 = rotl32(x1, rb[i]); x1 ^= x0; }
    x0 += ks2; x1 += ks0 + 2u;
    for (int i = 0; i < 4; i++) { x0 += x1; x1 = rotl32(x1, ra[i]); x1 ^= x0; }
    x0 += ks0; x1 += ks1 + 3u;
    for (int i = 0; i < 4; i++) { x0 += x1; x1 = rotl32(x1, rb[i]); x1 ^= x0; }
    x0 += ks1; x1 += ks2 + 4u;
    for (int i = 0; i < 4; i++) { x0 += x1; x1 = rotl32(x1, ra[i]); x1 ^= x0; }
    x0 += ks2; x1 += ks0 + 5u;
    *o0 = x0; *o1 = x1;
}

static inline TFKey tf_child(TFKey k, uint32_t j) {
    TFKey r; threefry2x32(k.hi, k.lo, 0u, j, &r.hi, &r.lo); return r;
}
static inline uint32_t tf_bits32(TFKey k, uint32_t i) {
    uint32_t a, b; threefry2x32(k.hi, k.lo, 0u, i, &a, &b); return a ^ b;
}

static void compute_host_idx(int* h_idx) {
    const int n = HW;
    TFKey key42 = {0u, 42u};
    TFKey k1 = tf_child(key42, 0u);
    TFKey k2 = tf_child(key42, 1u);

    std::vector<int> order(n);
    for (int i = 0; i < n; i++) order[i] = i;
    {
        TFKey cur = k1;
        std::vector<uint64_t> kv(n);
        std::vector<int> nx(n);
        for (int round = 0; round < 2; round++) {
            TFKey nkey = tf_child(cur, 0u);
            TFKey sub  = tf_child(cur, 1u);
            for (int i = 0; i < n; i++)
                kv[(size_t)i] = ((uint64_t)tf_bits32(sub, (uint32_t)i) << 32) |
                                (uint32_t)i;
            std::sort(kv.begin(), kv.end());
            for (int j = 0; j < n; j++)
                nx[(size_t)j] = order[(size_t)(uint32_t)kv[(size_t)j]];
            order.swap(nx);
            cur = nkey;
        }
    }

    float p0 = (float)(1.0 - 0.3), pq = (float)(0.3 / 4.0);
    float c[5];
    c[0] = p0;
    for (int j = 1; j < 5; j++) c[j] = c[j - 1] + pq;

    std::vector<uint8_t> rs(n);
    for (int i = 0; i < n; i++) {
        uint32_t bits = tf_bits32(k2, (uint32_t)i);
        uint32_t fb = (bits >> 9) | 0x3F800000u;
        float f; std::memcpy(&f, &fb, 4);
        f -= 1.0f;
        float r = c[4] * (1.0f - f);
        int ind = 0;
        while (ind < 5 && c[ind] < r) ind++;
        rs[(size_t)i] = (uint8_t)ind;
    }

    for (int i = 0; i < n; i++) h_idx[i] = i;
    for (int t = 0; t < n; t++) {
        const int a = order[(size_t)t];
        const int r = rs[(size_t)t];
        const int i = a / GW, j = a % GW;
        const int ii = (r == 1) ? (i + 1) % GH : (r == 2) ? (i + GH - 1) % GH : i;
        const int jj = (r == 3) ? (j + 1) % GW : (r == 4) ? (j + GW - 1) % GW : j;
        const int b = (r == 0) ? a : (ii * GW + jj);
        const int va = h_idx[a], vb = h_idx[b];
        h_idx[a] = vb; h_idx[b] = va;
    }
}

// ---------------------------------------------------------------------------

template <int Lc>
static void launch_pers(const float* x, float* out, const uint4* hidx,
                        int do_copy, int nblk) {
    const int smem = 2 * Lc * GW * (int)sizeof(float);
    cudaFuncSetAttribute(clop_pers<Lc>,
                         cudaFuncAttributeMaxDynamicSharedMemorySize, smem);
    clop_pers<Lc><<<nblk, NT, smem>>>(x, out, hidx, do_copy);
}

extern "C" void kernel_launch(void* const* d_in, const int* in_sizes, int n_in,
                              void* d_out, int out_size) {
    (void)in_sizes; (void)n_in; (void)out_size;

    static int h_idx[HW];
    alignas(16) static unsigned short h_idxl[HW];   // ATS-read by the kernel
    compute_host_idx(h_idx);

    // max toroidal row distance from each output row's band window (BAND=16)
    int D = 0;
    for (int i = 0; i < HW; i++) {
        const int r_out = i / GW;
        const int bandstart = (r_out / BAND) * BAND;
        const int r_src = h_idx[i] / GW;
        int dist = 0;
        if (r_src >= bandstart && r_src < bandstart + BAND) {
            dist = 0;
        } else {
            int dlo = (bandstart - r_src + GH) % GH;
            int dhi = (r_src - (bandstart + BAND - 1) + GH) % GH;
            dist = dlo < dhi ? dlo : dhi;
        }
        if (dist > D) D = dist;
    }

    const float* x = (const float*)d_in[0];
    float* out = (float*)d_out;

    if (D > 18) {
        // degenerate fallback: full-plane gather with absolute idx memcpy
        cudaFuncSetAttribute(clop_gather,
                             cudaFuncAttributeMaxDynamicSharedMemorySize,
                             HW * (int)sizeof(float));
        cudaMemcpyToSymbolAsync(g_idx, h_idx, sizeof(h_idx), 0,
                                cudaMemcpyHostToDevice, 0);
        clop_gather<<<NPLANES, 1024, HW * sizeof(float)>>>(x, out);
        return;
    }

    // ladder (double buffer => 2*Lc*896 B): Lc<=28 -> 4 blocks/SM (592),
    // Lc<=42 -> 3 blocks/SM (444), else 2 (296)
    int Lc, nblk;
    if (D <= 2)       { Lc = 20; nblk = 592; }
    else if (D <= 4)  { Lc = 24; nblk = 592; }
    else if (D <= 6)  { Lc = 28; nblk = 592; }
    else if (D <= 10) { Lc = 36; nblk = 444; }
    else              { Lc = 52; nblk = 296; }

    // window-relative row-major indices for the padded window
    const int Dp = (Lc - BAND) / 2;
    for (int i = 0; i < HW; i++) {
        const int r_out = i / GW;
        const int ws0 = (r_out / BAND) * BAND - Dp;
        const int r_src = h_idx[i] / GW;
        const int c_src = h_idx[i] % GW;
        int t = r_src - ws0;
        t %= GH; if (t < 0) t += GH;
        h_idxl[i] = (unsigned short)(t * GW + c_src);
    }

    int ats = 0;
    cudaDeviceGetAttribute(&ats, cudaDevAttrPageableMemoryAccess, 0);
    const uint4* hidx = reinterpret_cast<const uint4*>(h_idxl);

    if (!ats) {
        cudaMemcpyToSymbolAsync(g_idxl, h_idxl, sizeof(h_idxl), 0,
                                cudaMemcpyHostToDevice, 0);
    }
    const int do_copy = ats ? 1 : 0;

    if (Lc == 20)      launch_pers<20>(x, out, hidx, do_copy, nblk);
    else if (Lc == 24) launch_pers<24>(x, out, hidx, do_copy, nblk);
    else if (Lc == 28) launch_pers<28>(x, out, hidx, do_copy, nblk);
    else if (Lc == 36) launch_pers<36>(x, out, hidx, do_copy, nblk);
    else               launch_pers<52>(x, out, hidx, do_copy, nblk);
}